// round 1
// baseline (speedup 1.0000x reference)
#include <cuda_runtime.h>

#define TPB 128
#define NLAYER 4
#define LN_EPS 1e-5f

// Shared memory layout (all float, no implicit padding; ~86.3 KB total).
// Alignment: AW base offset = 20364 floats = 81456 B, 16B-aligned; W base 4096
// floats; all float4 accesses land on 16B boundaries.
struct __align__(16) Smem {
    float R[NLAYER][32][32];        // conv_root
    float W[NLAYER][3][32][32];     // conv_w
    float bias[NLAYER][32];         // conv_bias
    float Wf[6][32];                // W_f
    float bf[32];                   // b_f
    float lng[32];                  // ln_g
    float lnb[32];                  // ln_b
    float xs[64][33];               // node features, padded stride 33 (bank-conflict-free)
    float Lij[16][33];              // line sums over k, rows (i*4+j)
    float Lik[16][33];              // line sums over j, rows (i*4+k)
    float Si[4][33];                // plane sums over (j,k)
    float Sj[4][33];                // plane sums over (i,k)
    float Sk[4][33];                // plane sums over (i,j)
    float AW[3][16][36];            // agg_r @ W_r, 16 distinct rows per relation
};

__global__ __launch_bounds__(TPB) void gnn_frame0_kernel(
    const float* __restrict__ xx, const float* __restrict__ ss,
    const float* __restrict__ W_f, const float* __restrict__ b_f,
    const float* __restrict__ conv_w, const float* __restrict__ conv_root,
    const float* __restrict__ conv_bias, const float* __restrict__ ln_g,
    const float* __restrict__ ln_b, float* __restrict__ out)
{
    extern __shared__ __align__(16) unsigned char smem_raw[];
    Smem* s = reinterpret_cast<Smem*>(smem_raw);
    const int tid = threadIdx.x;
    const int b = blockIdx.x;

    // ---- stage all weights into shared (coalesced) ----
    for (int idx = tid; idx < 4096;  idx += TPB) (&s->R[0][0][0])[idx]    = conv_root[idx];
    for (int idx = tid; idx < 12288; idx += TPB) (&s->W[0][0][0][0])[idx] = conv_w[idx];
    for (int idx = tid; idx < 128;   idx += TPB) (&s->bias[0][0])[idx]    = conv_bias[idx];
    for (int idx = tid; idx < 192;   idx += TPB) (&s->Wf[0][0])[idx]      = W_f[idx];
    if (tid < 32) { s->bf[tid] = b_f[tid]; s->lng[tid] = ln_g[tid]; s->lnb[tid] = ln_b[tid]; }

    // thread -> (node, half-channel group)
    const int n  = tid >> 1;
    const int g  = tid & 1;
    const int c0 = g * 16;
    const int ii = n >> 4, jj = (n >> 2) & 3, kk = n & 3;

    __syncthreads();

    // ---- initial features: x0 = feats @ W_f + b_f  (t-coord = 0 for frame 0) ----
    {
        const float fi = ii * (1.0f / 3.0f);
        const float fj = jj * (1.0f / 3.0f);
        const float fk = kk * (1.0f / 3.0f);
        const float v  = xx[b * 512 + n];   // frame 0 = first 64 of each 512-node batch item
        const float m  = ss[b] * 0.125f;    // ss[:,0] / T
        #pragma unroll
        for (int q = 0; q < 16; q++) {
            int c = c0 + q;
            s->xs[n][c] = s->bf[c] + fi * s->Wf[0][c] + fj * s->Wf[1][c] + fk * s->Wf[2][c]
                          + v * s->Wf[4][c] + m * s->Wf[5][c];
        }
    }
    __syncthreads();

    // ---- 4 R-GCN layers ----
    for (int l = 0; l < NLAYER; l++) {
        // line sums: Lij[i*4+j][c] = sum_k x, Lik[i*4+k][c] = sum_j x
        for (int v = tid; v < 512; v += TPB) {
            int row = v >> 5, c = v & 31;
            s->Lij[row][c] = s->xs[row * 4 + 0][c] + s->xs[row * 4 + 1][c]
                           + s->xs[row * 4 + 2][c] + s->xs[row * 4 + 3][c];
            int base = (row >> 2) * 16 + (row & 3);
            s->Lik[row][c] = s->xs[base][c] + s->xs[base + 4][c]
                           + s->xs[base + 8][c] + s->xs[base + 12][c];
        }
        __syncthreads();
        // plane sums from line sums (128 values per array, one per thread)
        {
            int r4 = tid >> 5, c = tid & 31;
            s->Si[r4][c] = s->Lij[r4 * 4 + 0][c] + s->Lij[r4 * 4 + 1][c]
                         + s->Lij[r4 * 4 + 2][c] + s->Lij[r4 * 4 + 3][c];
            s->Sj[r4][c] = s->Lij[r4][c] + s->Lij[4 + r4][c] + s->Lij[8 + r4][c] + s->Lij[12 + r4][c];
            s->Sk[r4][c] = s->Lik[r4][c] + s->Lik[4 + r4][c] + s->Lik[8 + r4][c] + s->Lik[12 + r4][c];
        }
        __syncthreads();
        // AW[r][row] = agg_r(row) @ W[l][r]; 48 rows x 2 halves = 96 threads
        if (tid < 96) {
            int r = tid >> 5, sub = tid & 31, row = sub >> 1, cc = (sub & 1) * 16;
            const float* plane; const float* line;
            if (r == 0)      { plane = s->Si[row >> 2]; line = s->Lij[row]; }
            else if (r == 1) { plane = s->Sj[row & 3];  line = s->Lij[row]; }
            else             { plane = s->Sk[row & 3];  line = s->Lik[row]; }
            const float* Wl = &s->W[l][r][0][0];
            float acc[16];
            #pragma unroll
            for (int q = 0; q < 16; q++) acc[q] = 0.0f;
            #pragma unroll 4
            for (int k = 0; k < 32; k++) {
                float ak = (plane[k] - line[k]) * (1.0f / 12.0f);
                const float4* w4 = reinterpret_cast<const float4*>(Wl + k * 32 + cc);
                #pragma unroll
                for (int q4 = 0; q4 < 4; q4++) {
                    float4 w = w4[q4];
                    acc[q4 * 4 + 0] += ak * w.x;
                    acc[q4 * 4 + 1] += ak * w.y;
                    acc[q4 * 4 + 2] += ak * w.z;
                    acc[q4 * 4 + 3] += ak * w.w;
                }
            }
            float4* dst = reinterpret_cast<float4*>(&s->AW[r][row][cc]);
            #pragma unroll
            for (int q4 = 0; q4 < 4; q4++)
                dst[q4] = make_float4(acc[q4 * 4 + 0], acc[q4 * 4 + 1],
                                      acc[q4 * 4 + 2], acc[q4 * 4 + 3]);
        }
        __syncthreads();
        // node update: h = bias + AW0 + AW1 + AW2 + x @ R; then ReLU + LayerNorm
        {
            const int rij = (ii << 2) | jj;
            const int rik = (ii << 2) | kk;
            float h[16];
            const float4* b4 = reinterpret_cast<const float4*>(&s->bias[l][c0]);
            const float4* a0 = reinterpret_cast<const float4*>(&s->AW[0][rij][c0]);
            const float4* a1 = reinterpret_cast<const float4*>(&s->AW[1][rij][c0]);
            const float4* a2 = reinterpret_cast<const float4*>(&s->AW[2][rik][c0]);
            #pragma unroll
            for (int q4 = 0; q4 < 4; q4++) {
                float4 vb = b4[q4], v0 = a0[q4], v1 = a1[q4], v2 = a2[q4];
                h[q4 * 4 + 0] = vb.x + v0.x + v1.x + v2.x;
                h[q4 * 4 + 1] = vb.y + v0.y + v1.y + v2.y;
                h[q4 * 4 + 2] = vb.z + v0.z + v1.z + v2.z;
                h[q4 * 4 + 3] = vb.w + v0.w + v1.w + v2.w;
            }
            const float* Rl   = &s->R[l][0][0];
            const float* xrow = s->xs[n];
            #pragma unroll 4
            for (int k = 0; k < 32; k++) {
                float xv = xrow[k];
                const float4* w4 = reinterpret_cast<const float4*>(Rl + k * 32 + c0);
                #pragma unroll
                for (int q4 = 0; q4 < 4; q4++) {
                    float4 w = w4[q4];
                    h[q4 * 4 + 0] += xv * w.x;
                    h[q4 * 4 + 1] += xv * w.y;
                    h[q4 * 4 + 2] += xv * w.z;
                    h[q4 * 4 + 3] += xv * w.w;
                }
            }
            float ssum = 0.0f;
            #pragma unroll
            for (int q = 0; q < 16; q++) { h[q] = fmaxf(h[q], 0.0f); ssum += h[q]; }
            ssum += __shfl_xor_sync(0xffffffffu, ssum, 1);
            float mu = ssum * (1.0f / 32.0f);
            float vsum = 0.0f;
            #pragma unroll
            for (int q = 0; q < 16; q++) { float d = h[q] - mu; h[q] = d; vsum += d * d; }
            vsum += __shfl_xor_sync(0xffffffffu, vsum, 1);
            float rs = rsqrtf(vsum * (1.0f / 32.0f) + LN_EPS);
            #pragma unroll
            for (int q = 0; q < 16; q++) {
                int c = c0 + q;
                s->xs[n][c] = h[q] * rs * s->lng[c] + s->lnb[c];
            }
        }
        __syncthreads();
    }

    // ---- output: three axis-means over the 4x4x4 frame, (48, 32) per batch item ----
    float* outb = out + (size_t)b * 48 * 32;
    for (int v = tid; v < 1536; v += TPB) {
        int o = v >> 5, c = v & 31;
        float val;
        if (o < 16) {               // mean over i; o = j*4+k
            val = s->xs[o][c] + s->xs[o + 16][c] + s->xs[o + 32][c] + s->xs[o + 48][c];
        } else if (o < 32) {        // mean over j; (o-16) = i*4+k
            int oo = o - 16; int base = (oo >> 2) * 16 + (oo & 3);
            val = s->xs[base][c] + s->xs[base + 4][c] + s->xs[base + 8][c] + s->xs[base + 12][c];
        } else {                    // mean over k; (o-32) = i*4+j
            int oo = o - 32; int base = (oo >> 2) * 16 + (oo & 3) * 4;
            val = s->xs[base][c] + s->xs[base + 1][c] + s->xs[base + 2][c] + s->xs[base + 3][c];
        }
        outb[o * 32 + c] = val * 0.25f;
    }
}

extern "C" void kernel_launch(void* const* d_in, const int* in_sizes, int n_in,
                              void* d_out, int out_size) {
    const float* xx        = (const float*)d_in[0];
    const float* ss        = (const float*)d_in[1];
    const float* W_f       = (const float*)d_in[2];
    const float* b_f       = (const float*)d_in[3];
    const float* conv_w    = (const float*)d_in[4];
    const float* conv_root = (const float*)d_in[5];
    const float* conv_bias = (const float*)d_in[6];
    const float* ln_g      = (const float*)d_in[7];
    const float* ln_b      = (const float*)d_in[8];
    // d_in[9] = src, d_in[10] = dst: unused — aggregation has a closed form.

    const int B = in_sizes[1];  // ss has one entry per batch item

    cudaFuncSetAttribute(gnn_frame0_kernel,
                         cudaFuncAttributeMaxDynamicSharedMemorySize,
                         (int)sizeof(Smem));
    gnn_frame0_kernel<<<B, TPB, sizeof(Smem)>>>(
        xx, ss, W_f, b_f, conv_w, conv_root, conv_bias, ln_g, ln_b,
        (float*)d_out);
}

// round 2
// speedup vs baseline: 1.1651x; 1.1651x over previous
#include <cuda_runtime.h>

#define TPB 256
#define NLAYER 4
#define LN_EPS 1e-5f

// ~95.4 KB shared per block -> 2 blocks/SM co-resident (grid=256 on 148 SMs).
struct __align__(16) Smem {
    float R[NLAYER][32][32];        // conv_root              (offset 0)
    float W[NLAYER][3][32][32];     // conv_w                 (4096 f)
    float bias[NLAYER][32];         // conv_bias              (16512 f)
    float Wf[6][32];                // W_f
    float bf[32];
    float lng[32];
    float lnb[32];
    float xs[64][33];               // node features, stride 33 (scalar access)
    float Lij[16][33];              // line sums over k, rows (i*4+j)
    float Lik[16][33];              // line sums over j, rows (i*4+k)
    float Si[4][33];                // plane sums over (j,k)
    float Sj[4][33];                // plane sums over (i,k)
    float Sk[4][33];                // plane sums over (i,j)
    float AW[3][16][36];            // agg_r @ W_r  (stride 36 -> float4 ok)
    float Hroot[64][36];            // x @ R        (stride 36 -> float4 ok)
    float zero[36];                 // uniform zero operand for root rows
};

__global__ __launch_bounds__(TPB) void gnn_frame0_kernel(
    const float* __restrict__ xx, const float* __restrict__ ss,
    const float* __restrict__ W_f, const float* __restrict__ b_f,
    const float* __restrict__ conv_w, const float* __restrict__ conv_root,
    const float* __restrict__ conv_bias, const float* __restrict__ ln_g,
    const float* __restrict__ ln_b, float* __restrict__ out)
{
    extern __shared__ __align__(16) unsigned char smem_raw[];
    Smem* s = reinterpret_cast<Smem*>(smem_raw);
    const int tid = threadIdx.x;
    const int b = blockIdx.x;

    // ---- stage weights (float4, coalesced) ----
    {
        float4*       dR = reinterpret_cast<float4*>(&s->R[0][0][0]);
        const float4* gR = reinterpret_cast<const float4*>(conv_root);
        for (int i = tid; i < 1024; i += TPB) dR[i] = gR[i];
        float4*       dW = reinterpret_cast<float4*>(&s->W[0][0][0][0]);
        const float4* gW = reinterpret_cast<const float4*>(conv_w);
        for (int i = tid; i < 3072; i += TPB) dW[i] = gW[i];
        float4*       dB = reinterpret_cast<float4*>(&s->bias[0][0]);
        const float4* gB = reinterpret_cast<const float4*>(conv_bias);
        if (tid < 32) dB[tid] = gB[tid];
        float4*       dF = reinterpret_cast<float4*>(&s->Wf[0][0]);
        const float4* gF = reinterpret_cast<const float4*>(W_f);
        if (tid < 48) dF[tid] = gF[tid];
        if (tid >= 64 && tid < 96)  s->bf[tid - 64]  = b_f[tid - 64];
        if (tid >= 96 && tid < 128) s->lng[tid - 96] = ln_g[tid - 96];
        if (tid >= 128 && tid < 160) s->lnb[tid - 128] = ln_b[tid - 128];
        if (tid >= 160 && tid < 196) s->zero[tid - 160] = 0.0f;
    }

    // thread -> (node, 8-channel group) for init / combine phases
    const int nd  = tid >> 2;
    const int ch0 = (tid & 3) * 8;
    const int ii = nd >> 4, jj = (nd >> 2) & 3, kk = nd & 3;
    const int rij = (ii << 2) | jj;
    const int rik = (ii << 2) | kk;

    __syncthreads();

    // ---- initial features (frame t=0): x0 = feats @ W_f + b_f ----
    {
        const float fi = ii * (1.0f / 3.0f);
        const float fj = jj * (1.0f / 3.0f);
        const float fk = kk * (1.0f / 3.0f);
        const float v  = xx[b * 512 + nd];   // frame 0 = first 64 nodes
        const float m  = ss[b] * 0.125f;     // ss / T
        #pragma unroll
        for (int q = 0; q < 8; q++) {
            int c = ch0 + q;
            s->xs[nd][c] = s->bf[c] + fi * s->Wf[0][c] + fj * s->Wf[1][c]
                         + fk * s->Wf[2][c] + v * s->Wf[4][c] + m * s->Wf[5][c];
        }
    }
    __syncthreads();

    // ---- matmul-phase thread mapping (224 active): 112 rows x 2 halves ----
    const int row  = tid >> 1;
    const int cc   = (tid & 1) * 16;
    const float* opA = s->zero;
    const float* opB = s->zero;
    const float* WlBase;            // per-layer offset added in loop
    float* dst = s->zero;           // dummy (inactive threads never store)
    float scale = 0.0f;
    int  wOff = 0;                  // float offset of this row's matrix within its table
    bool rootRow = false;
    if (tid < 224) {
        if (row < 48) {
            int r = row >> 4, sr = row & 15;
            wOff = r * 1024;
            dst  = &s->AW[r][sr][cc];
            opB  = (r == 2) ? s->Lik[sr] : s->Lij[sr];
            opA  = (r == 0) ? s->Si[sr >> 2] : (r == 1 ? s->Sj[sr & 3] : s->Sk[sr & 3]);
            scale = 1.0f / 12.0f;
            rootRow = false;
        } else {
            int n2 = row - 48;
            dst  = &s->Hroot[n2][cc];
            opA  = s->xs[n2];
            opB  = s->zero;
            scale = 1.0f;
            rootRow = true;
        }
    }

    // ---- 4 R-GCN layers ----
    for (int l = 0; l < NLAYER; l++) {
        // Phase A: line sums + plane sums, all straight from xs (one sync).
        #pragma unroll
        for (int v = tid; v < 512; v += TPB) {
            int rr = v >> 5, c = v & 31;
            s->Lij[rr][c] = s->xs[rr * 4 + 0][c] + s->xs[rr * 4 + 1][c]
                          + s->xs[rr * 4 + 2][c] + s->xs[rr * 4 + 3][c];
            int base = (rr >> 2) * 16 + (rr & 3);
            s->Lik[rr][c] = s->xs[base][c] + s->xs[base + 4][c]
                          + s->xs[base + 8][c] + s->xs[base + 12][c];
        }
        for (int t = tid; t < 384; t += TPB) {
            int which = t >> 7, idx = (t >> 5) & 3, c = t & 31;
            float acc = 0.0f;
            if (which == 0) {          // Si[i] = sum over (j,k)
                #pragma unroll
                for (int m = 0; m < 16; m++) acc += s->xs[idx * 16 + m][c];
                s->Si[idx][c] = acc;
            } else if (which == 1) {   // Sj[j] = sum over (i,k)
                #pragma unroll
                for (int i2 = 0; i2 < 4; i2++)
                    #pragma unroll
                    for (int k2 = 0; k2 < 4; k2++)
                        acc += s->xs[i2 * 16 + idx * 4 + k2][c];
                s->Sj[idx][c] = acc;
            } else {                   // Sk[k] = sum over (i,j)
                #pragma unroll
                for (int i2 = 0; i2 < 4; i2++)
                    #pragma unroll
                    for (int j2 = 0; j2 < 4; j2++)
                        acc += s->xs[i2 * 16 + j2 * 4 + idx][c];
                s->Sk[idx][c] = acc;
            }
        }
        __syncthreads();

        // Phase B: all 112 matmul rows (48 AW + 64 root), 224 threads, 16 chains.
        if (tid < 224) {
            const float* Wl = rootRow ? &s->R[l][0][0] : (&s->W[l][0][0][0] + wOff);
            float acc[16];
            #pragma unroll
            for (int q = 0; q < 16; q++) acc[q] = 0.0f;
            #pragma unroll 4
            for (int k = 0; k < 32; k++) {
                float a = (opA[k] - opB[k]) * scale;
                const float4* w4 = reinterpret_cast<const float4*>(Wl + k * 32 + cc);
                #pragma unroll
                for (int q4 = 0; q4 < 4; q4++) {
                    float4 w = w4[q4];
                    acc[q4 * 4 + 0] += a * w.x;
                    acc[q4 * 4 + 1] += a * w.y;
                    acc[q4 * 4 + 2] += a * w.z;
                    acc[q4 * 4 + 3] += a * w.w;
                }
            }
            float4* d4 = reinterpret_cast<float4*>(dst);
            #pragma unroll
            for (int q4 = 0; q4 < 4; q4++)
                d4[q4] = make_float4(acc[q4 * 4 + 0], acc[q4 * 4 + 1],
                                     acc[q4 * 4 + 2], acc[q4 * 4 + 3]);
        }
        __syncthreads();

        // Phase C: combine + ReLU + LayerNorm (64 nodes x 4 groups of 8 ch).
        {
            float h[8];
            const float4* b4 = reinterpret_cast<const float4*>(&s->bias[l][ch0]);
            const float4* a0 = reinterpret_cast<const float4*>(&s->AW[0][rij][ch0]);
            const float4* a1 = reinterpret_cast<const float4*>(&s->AW[1][rij][ch0]);
            const float4* a2 = reinterpret_cast<const float4*>(&s->AW[2][rik][ch0]);
            const float4* hr = reinterpret_cast<const float4*>(&s->Hroot[nd][ch0]);
            #pragma unroll
            for (int q4 = 0; q4 < 2; q4++) {
                float4 vb = b4[q4], v0 = a0[q4], v1 = a1[q4], v2 = a2[q4], vr = hr[q4];
                h[q4 * 4 + 0] = vb.x + v0.x + v1.x + v2.x + vr.x;
                h[q4 * 4 + 1] = vb.y + v0.y + v1.y + v2.y + vr.y;
                h[q4 * 4 + 2] = vb.z + v0.z + v1.z + v2.z + vr.z;
                h[q4 * 4 + 3] = vb.w + v0.w + v1.w + v2.w + vr.w;
            }
            float ssum = 0.0f;
            #pragma unroll
            for (int q = 0; q < 8; q++) { h[q] = fmaxf(h[q], 0.0f); ssum += h[q]; }
            ssum += __shfl_xor_sync(0xffffffffu, ssum, 1);
            ssum += __shfl_xor_sync(0xffffffffu, ssum, 2);
            float mu = ssum * (1.0f / 32.0f);
            float vsum = 0.0f;
            #pragma unroll
            for (int q = 0; q < 8; q++) { float d = h[q] - mu; h[q] = d; vsum += d * d; }
            vsum += __shfl_xor_sync(0xffffffffu, vsum, 1);
            vsum += __shfl_xor_sync(0xffffffffu, vsum, 2);
            float rs = rsqrtf(vsum * (1.0f / 32.0f) + LN_EPS);
            #pragma unroll
            for (int q = 0; q < 8; q++) {
                int c = ch0 + q;
                s->xs[nd][c] = h[q] * rs * s->lng[c] + s->lnb[c];
            }
        }
        __syncthreads();
    }

    // ---- output: three axis-means over the 4x4x4 frame -> (48, 32) ----
    float* outb = out + (size_t)b * 48 * 32;
    #pragma unroll
    for (int v = tid; v < 1536; v += TPB) {
        int o = v >> 5, c = v & 31;
        float val;
        if (o < 16) {               // mean over i; o = j*4+k
            val = s->xs[o][c] + s->xs[o + 16][c] + s->xs[o + 32][c] + s->xs[o + 48][c];
        } else if (o < 32) {        // mean over j; (o-16) = i*4+k
            int oo = o - 16; int base = (oo >> 2) * 16 + (oo & 3);
            val = s->xs[base][c] + s->xs[base + 4][c] + s->xs[base + 8][c] + s->xs[base + 12][c];
        } else {                    // mean over k; (o-32) = i*4+j
            int oo = o - 32; int base = (oo >> 2) * 16 + (oo & 3) * 4;
            val = s->xs[base][c] + s->xs[base + 1][c] + s->xs[base + 2][c] + s->xs[base + 3][c];
        }
        outb[o * 32 + c] = val * 0.25f;
    }
}

extern "C" void kernel_launch(void* const* d_in, const int* in_sizes, int n_in,
                              void* d_out, int out_size) {
    const float* xx        = (const float*)d_in[0];
    const float* ss        = (const float*)d_in[1];
    const float* W_f       = (const float*)d_in[2];
    const float* b_f       = (const float*)d_in[3];
    const float* conv_w    = (const float*)d_in[4];
    const float* conv_root = (const float*)d_in[5];
    const float* conv_bias = (const float*)d_in[6];
    const float* ln_g      = (const float*)d_in[7];
    const float* ln_b      = (const float*)d_in[8];
    // d_in[9]/d_in[10] (src/dst) unused: aggregation has a closed form.

    const int B = in_sizes[1];

    cudaFuncSetAttribute(gnn_frame0_kernel,
                         cudaFuncAttributeMaxDynamicSharedMemorySize,
                         (int)sizeof(Smem));
    gnn_frame0_kernel<<<B, TPB, sizeof(Smem)>>>(
        xx, ss, W_f, b_f, conv_w, conv_root, conv_bias, ln_g, ln_b,
        (float*)d_out);
}